// round 3
// baseline (speedup 1.0000x reference)
#include <cuda_runtime.h>
#include <cuda_bf16.h>
#include <cstdint>

// Capsule routing: B=2048, R=64, H=512, NUM_ITER=3.  Output final_vec [B,H] f32.
//
// Collapsed algorithm (b_ij accumulates x*v):
//   s0 = mean_r x;               v1 = squash(s0)
//   softmax_r(x * v1)        ->  v2 = squash(sum_r c x)
//   softmax_r(x * (v1+v2))   ->  v3 = squash(sum_r c x)   -> output v3
//
// R3 layout: 2-CTA cluster per batch. Each CTA: 512 threads = 256 h-cols x
// 2 row-halves (32 rows per thread in registers). <=64 regs (launch_bounds
// (512,2)) -> 2 independent CTAs resident per SM -> load phase of one CTA
// overlaps compute phase of the other (breaks the R1/R2 phase convoy).
// The per-batch squash norm couples the 2 CTAs of a cluster: exchanged via
// one DSMEM scalar per iteration (3 slots, no reuse) + cluster barriers.

#define B_DIM 2048
#define R_DIM 64
#define H_DIM 512
#define NT 512           // threads per CTA
#define COLS 256         // h-cols per CTA
#define R_HALF 32

__device__ __forceinline__ float fast_exp2(float x) {
    float r;
    asm("ex2.approx.ftz.f32 %0, %1;" : "=f"(r) : "f"(x));
    return r;
}

__device__ __forceinline__ uint32_t smem_u32(const void* p) {
    return (uint32_t)__cvta_generic_to_shared(p);
}

__device__ __forceinline__ void st_peer_f32(uint32_t local_addr, uint32_t peer_rank, float v) {
    uint32_t remote;
    asm volatile("mapa.shared::cluster.u32 %0, %1, %2;"
                 : "=r"(remote) : "r"(local_addr), "r"(peer_rank));
    asm volatile("st.shared::cluster.f32 [%0], %1;" :: "r"(remote), "f"(v));
}

__device__ __forceinline__ void cluster_sync_() {
    asm volatile("barrier.cluster.arrive.aligned;" ::: "memory");
    asm volatile("barrier.cluster.wait.aligned;" ::: "memory");
}

// CTA-wide sum over 512 threads (16 warps); result broadcast to all threads.
__device__ __forceinline__ float block_sum(float val, float* sred) {
    #pragma unroll
    for (int o = 16; o > 0; o >>= 1)
        val += __shfl_xor_sync(0xffffffffu, val, o);
    int wid = threadIdx.x >> 5;
    int lid = threadIdx.x & 31;
    __syncthreads();                      // also fences prior sh_* reads
    if (lid == 0) sred[wid] = val;
    __syncthreads();
    if (threadIdx.x < 32) {
        float v = (lid < 16) ? sred[lid] : 0.0f;
        #pragma unroll
        for (int o = 8; o > 0; o >>= 1)
            v += __shfl_xor_sync(0xffffffffu, v, o);
        if (lid == 0) sred[0] = v;
    }
    __syncthreads();
    return sred[0];
}

__global__ void __launch_bounds__(NT, 2) __cluster_dims__(2, 1, 1)
capsule_kernel(const float* __restrict__ x, float* __restrict__ out) {
    __shared__ float sh_a[NT];
    __shared__ float sh_b[NT];
    __shared__ float sh_c[NT];
    __shared__ float sred[16];
    __shared__ float peer_slot[3];   // written remotely by the peer CTA

    const int tid  = threadIdx.x;
    const int col  = tid & (COLS - 1);          // 0..255 local col
    const int half = tid >> 8;                  // 0/1 row-half
    const int prt  = tid ^ COLS;                // partner thread (other half)
    const uint32_t rank = (uint32_t)(blockIdx.x & 1);
    const int b    = blockIdx.x >> 1;
    const int h    = (int)rank * COLS + col;    // global h for this thread

    const float* xb = x + (size_t)b * (R_DIM * H_DIM)
                        + (size_t)(half * R_HALF) * H_DIM + h;

    // ---- load 32 rows; fused partial sum / max / min ----
    float xr[R_HALF];
    float psum = 0.0f;
    float pmax = -3.402823466e38f;
    float pmin =  3.402823466e38f;
    #pragma unroll
    for (int i = 0; i < R_HALF; i++) {
        xr[i] = __ldg(xb + i * H_DIM);
        psum += xr[i];
        pmax = fmaxf(pmax, xr[i]);
        pmin = fminf(pmin, xr[i]);
    }
    sh_a[tid] = psum;
    sh_b[tid] = pmax;
    sh_c[tid] = pmin;
    __syncthreads();
    const float sum0 = psum + sh_a[prt];
    const float xmax = fmaxf(pmax, sh_b[prt]);
    const float xmin = fminf(pmin, sh_c[prt]);

    const uint32_t slot_base = smem_u32(peer_slot);
    const uint32_t peer = rank ^ 1u;
    const float L2E = 1.4426950408889634f;

    // ---- iter 0: uniform coefficients -> mean over r, squash ----
    float s = sum0 * (1.0f / (float)R_DIM);
    float partial = block_sum(0.5f * s * s, sred);   // each col pair counts once
    if (tid == 0) st_peer_f32(slot_base + 0u, peer, partial);
    cluster_sync_();
    float norm = partial + peer_slot[0];

    float sq = sqrtf(norm);
    float f  = sq / (1.0f + sq);
    float v  = f * s;
    float w  = v;

    // ---- iterations 1 and 2 ----
    #pragma unroll
    for (int it = 0; it < 2; it++) {
        float wl = w * L2E;
        float m  = fmaxf(wl * xmax, wl * xmin);   // max_r(x_r * wl)
        float pse  = 0.0f;
        float psex = 0.0f;
        #pragma unroll
        for (int i = 0; i < R_HALF; i++) {
            float e = fast_exp2(fmaf(xr[i], wl, -m));
            pse += e;
            psex = fmaf(e, xr[i], psex);
        }
        sh_a[tid] = pse;      // safe: last sh_a read was before block_sum's sync
        sh_b[tid] = psex;
        __syncthreads();
        float se  = pse  + sh_a[prt];
        float sex = psex + sh_b[prt];
        s = sex / se;

        partial = block_sum(0.5f * s * s, sred);
        if (tid == 0) st_peer_f32(slot_base + 4u * (it + 1), peer, partial);
        cluster_sync_();
        norm = partial + peer_slot[it + 1];

        sq = sqrtf(norm);
        f  = sq / (1.0f + sq);
        v  = f * s;
        w += v;
    }

    if (half == 0)
        out[(size_t)b * H_DIM + h] = v;
}

extern "C" void kernel_launch(void* const* d_in, const int* in_sizes, int n_in,
                              void* d_out, int out_size) {
    const float* x = (const float*)d_in[0];
    float* out = (float*)d_out;
    capsule_kernel<<<2 * B_DIM, NT>>>(x, out);
}

// round 4
// speedup vs baseline: 1.3798x; 1.3798x over previous
#include <cuda_runtime.h>
#include <cuda_bf16.h>
#include <cstdint>

// Capsule routing: B=2048, R=64, H=512, NUM_ITER=3.  Output final_vec [B,H] f32.
//
// R4: persistent pipeline. 148 CTAs x 1024 threads; each CTA handles ~14
// batches. Per batch: TMA (cp.async.bulk) stages the batch's 128KB into smem;
// threads copy it to registers (xr[32]) in one LDS pass, then the NEXT batch's
// TMA is issued so it streams from HBM concurrently with this batch's
// MUFU-heavy softmax iterations. Breaks the load/compute phase convoy that
// pinned R1-R3 at ~46% DRAM + ~40% issue (sum of floors instead of max).

#define B_DIM 2048
#define R_DIM 64
#define H_DIM 512
#define NT 1024
#define R_HALF 32
#define GRID 148
#define BATCH_BYTES (R_DIM * H_DIM * 4)   // 131072

__device__ __forceinline__ float fast_exp2(float x) {
    float r;
    asm("ex2.approx.ftz.f32 %0, %1;" : "=f"(r) : "f"(x));
    return r;
}

// Block-wide sum over 1024 threads (32 warps); result broadcast to all.
__device__ __forceinline__ float block_sum(float val, float* sred) {
    #pragma unroll
    for (int o = 16; o > 0; o >>= 1)
        val += __shfl_xor_sync(0xffffffffu, val, o);
    int wid = threadIdx.x >> 5;
    int lid = threadIdx.x & 31;
    __syncthreads();
    if (lid == 0) sred[wid] = val;
    __syncthreads();
    if (threadIdx.x < 32) {
        float v = sred[lid];
        #pragma unroll
        for (int o = 16; o > 0; o >>= 1)
            v += __shfl_xor_sync(0xffffffffu, v, o);
        if (lid == 0) sred[0] = v;
    }
    __syncthreads();
    return sred[0];
}

__device__ __forceinline__ void mbar_wait_acq(uint32_t mbar, uint32_t parity) {
    asm volatile(
        "{\n\t"
        ".reg .pred P;\n\t"
        "WAIT_LOOP_%=:\n\t"
        "mbarrier.try_wait.parity.acquire.cta.shared::cta.b64 P, [%0], %1, 0x989680;\n\t"
        "@P bra.uni WAIT_DONE_%=;\n\t"
        "bra.uni WAIT_LOOP_%=;\n\t"
        "WAIT_DONE_%=:\n\t"
        "}"
        :: "r"(mbar), "r"(parity) : "memory");
}

__global__ void __launch_bounds__(NT, 1)
capsule_kernel(const float* __restrict__ x, float* __restrict__ out) {
    extern __shared__ float sbuf[];               // [R_DIM * H_DIM] staging
    __shared__ float sh_a[NT];
    __shared__ float sh_b[NT];
    __shared__ float sh_c[NT];
    __shared__ float sred[32];
    __shared__ uint64_t mbar_storage;

    const uint32_t mbar = (uint32_t)__cvta_generic_to_shared(&mbar_storage);
    const uint32_t sbuf_addr = (uint32_t)__cvta_generic_to_shared(sbuf);

    const int tid  = threadIdx.x;
    const int h    = tid & (H_DIM - 1);
    const int half = tid >> 9;                    // 0/1: row half
    const int prt  = tid ^ H_DIM;                 // partner thread

    if (tid == 0)
        asm volatile("mbarrier.init.shared.b64 [%0], %1;" :: "r"(mbar), "r"(1));
    __syncthreads();

    // Issue the first TMA prefetch.
    int b = blockIdx.x;
    if (tid == 0 && b < B_DIM) {
        asm volatile("mbarrier.arrive.expect_tx.shared.b64 _, [%0], %1;"
                     :: "r"(mbar), "r"(BATCH_BYTES));
        const char* src = (const char*)(x + (size_t)b * (R_DIM * H_DIM));
        #pragma unroll
        for (int c = 0; c < 4; c++) {
            asm volatile(
                "cp.async.bulk.shared::cta.global.mbarrier::complete_tx::bytes "
                "[%0], [%1], %2, [%3];"
                :: "r"(sbuf_addr + c * 32768u), "l"(src + c * 32768),
                   "r"(32768), "r"(mbar) : "memory");
        }
    }

    uint32_t phase = 0;
    const float L2E = 1.4426950408889634f;

    for (; b < B_DIM; b += GRID) {
        mbar_wait_acq(mbar, phase);
        phase ^= 1;

        // ---- smem -> registers, fused partial sum/max/min ----
        float xr[R_HALF];
        float psum = 0.0f;
        float pmax = -3.402823466e38f;
        float pmin =  3.402823466e38f;
        const float* bp = sbuf + (size_t)(half * R_HALF) * H_DIM + h;
        #pragma unroll
        for (int i = 0; i < R_HALF; i++) {
            xr[i] = bp[i * H_DIM];
            psum += xr[i];
            pmax = fmaxf(pmax, xr[i]);
            pmin = fminf(pmin, xr[i]);
        }
        sh_a[tid] = psum;
        sh_b[tid] = pmax;
        sh_c[tid] = pmin;
        __syncthreads();   // all sbuf reads done & consumed -> safe to refill

        // Prefetch the NEXT batch; streams during this batch's compute.
        int nb = b + GRID;
        if (tid == 0 && nb < B_DIM) {
            asm volatile("mbarrier.arrive.expect_tx.shared.b64 _, [%0], %1;"
                         :: "r"(mbar), "r"(BATCH_BYTES));
            const char* src = (const char*)(x + (size_t)nb * (R_DIM * H_DIM));
            #pragma unroll
            for (int c = 0; c < 4; c++) {
                asm volatile(
                    "cp.async.bulk.shared::cta.global.mbarrier::complete_tx::bytes "
                    "[%0], [%1], %2, [%3];"
                    :: "r"(sbuf_addr + c * 32768u), "l"(src + c * 32768),
                       "r"(32768), "r"(mbar) : "memory");
            }
        }

        const float sum0 = psum + sh_a[prt];
        const float xmax = fmaxf(pmax, sh_b[prt]);
        const float xmin = fminf(pmin, sh_c[prt]);

        // ---- iter 0: uniform coefficients -> mean over r, squash ----
        float s = sum0 * (1.0f / (float)R_DIM);
        float norm = block_sum(0.5f * s * s, sred);
        float sq = sqrtf(norm);
        float f  = sq / (1.0f + sq);
        float v  = f * s;
        float w  = v;

        // ---- iterations 1 and 2 ----
        #pragma unroll
        for (int it = 0; it < 2; it++) {
            float wl = w * L2E;
            float m  = fmaxf(wl * xmax, wl * xmin);
            float pse  = 0.0f;
            float psex = 0.0f;
            #pragma unroll
            for (int i = 0; i < R_HALF; i++) {
                float e = fast_exp2(fmaf(xr[i], wl, -m));
                pse += e;
                psex = fmaf(e, xr[i], psex);
            }
            sh_a[tid] = pse;     // last sh_a read was before block_sum's sync
            sh_b[tid] = psex;
            __syncthreads();
            float se  = pse  + sh_a[prt];
            float sex = psex + sh_b[prt];
            s = sex / se;

            norm = block_sum(0.5f * s * s, sred);
            sq = sqrtf(norm);
            f  = sq / (1.0f + sq);
            v  = f * s;
            w += v;
        }

        if (half == 0)
            out[(size_t)b * H_DIM + h] = v;
    }
}

extern "C" void kernel_launch(void* const* d_in, const int* in_sizes, int n_in,
                              void* d_out, int out_size) {
    const float* x = (const float*)d_in[0];
    float* out = (float*)d_out;
    cudaFuncSetAttribute(capsule_kernel,
                         cudaFuncAttributeMaxDynamicSharedMemorySize,
                         BATCH_BYTES);
    capsule_kernel<<<GRID, NT, BATCH_BYTES>>>(x, out);
}